// round 2
// baseline (speedup 1.0000x reference)
#include <cuda_runtime.h>

#define B_  4
#define T_  2048
#define C_  1024
#define NH_ 16
#define D_  64
#define BT_ (B_ * T_)      // 8192
#define C3_ (3 * C_)       // 3072

// Scratch buffers (no allocation allowed) — zero-init .bss style device globals.
__device__ float g_qkv[BT_ * C3_];   // [8192, 3072]  q|k|v, biases folded, q pre-scaled by 1/sqrt(D)
__device__ float g_y[BT_ * C_];      // [8192, 1024]  attention output, head-major columns

// ---------------------------------------------------------------------------
// SGEMM: C[M,N] = A[M,K] @ W[K,N] + epilogue.  BM=BN=128, BK=8, 256 threads,
// 8x8 microtile arranged as 2x2 blocks of 4x4 (conflict-free float4 fragments).
// MODE 0: qkv epilogue (b_attn; +bQ & *0.125 for q cols; +bK for k cols)
// MODE 1: proj epilogue (b_proj)
// ---------------------------------------------------------------------------
template<int MODE>
__global__ __launch_bounds__(256) void sgemm_kernel(
    const float* __restrict__ A, const float* __restrict__ W,
    const float* __restrict__ bias,
    const float* __restrict__ bQ, const float* __restrict__ bK,
    float* __restrict__ Cout, int M, int N, int K)
{
    __shared__ float As[8][128];   // A tile transposed: As[k][m]
    __shared__ float Bs[8][128];   // B tile natural:    Bs[k][n]

    const int tid = threadIdx.x;
    const int tx = tid & 15, ty = tid >> 4;
    const int crow = blockIdx.y * 128, ccol = blockIdx.x * 128;

    // global-load assignments
    const int arow = tid >> 1, acol = (tid & 1) * 4;   // 128 rows x 8 cols
    const int brow = tid >> 5, bcol = (tid & 31) * 4;  // 8 rows x 128 cols
    const float* Ag = A + (size_t)(crow + arow) * K + acol;
    const float* Wg = W + (size_t)brow * N + (ccol + bcol);

    float c[8][8];
    #pragma unroll
    for (int i = 0; i < 8; i++)
        #pragma unroll
        for (int j = 0; j < 8; j++) c[i][j] = 0.f;

    float4 pa = *(const float4*)Ag;
    float4 pb = *(const float4*)Wg;
    const int nk = K >> 3;

    for (int kt = 0; kt < nk; kt++) {
        As[acol + 0][arow] = pa.x;
        As[acol + 1][arow] = pa.y;
        As[acol + 2][arow] = pa.z;
        As[acol + 3][arow] = pa.w;
        *(float4*)&Bs[brow][bcol] = pb;
        __syncthreads();

        if (kt + 1 < nk) {   // register prefetch of next tile
            pa = *(const float4*)(Ag + (kt + 1) * 8);
            pb = *(const float4*)(Wg + (size_t)(kt + 1) * 8 * N);
        }

        #pragma unroll
        for (int k = 0; k < 8; k++) {
            float a[8], bb[8];
            *(float4*)&a[0]  = *(const float4*)&As[k][ty * 4];
            *(float4*)&a[4]  = *(const float4*)&As[k][64 + ty * 4];
            *(float4*)&bb[0] = *(const float4*)&Bs[k][tx * 4];
            *(float4*)&bb[4] = *(const float4*)&Bs[k][64 + tx * 4];
            #pragma unroll
            for (int i = 0; i < 8; i++)
                #pragma unroll
                for (int j = 0; j < 8; j++)
                    c[i][j] = fmaf(a[i], bb[j], c[i][j]);
        }
        __syncthreads();
    }

    // epilogue (column-region branches are uniform: region boundaries are multiples of 128)
    #pragma unroll
    for (int ri = 0; ri < 2; ri++)
    #pragma unroll
    for (int ii = 0; ii < 4; ii++) {
        const int r = crow + ri * 64 + ty * 4 + ii;
        #pragma unroll
        for (int ci = 0; ci < 2; ci++) {
            const int n0 = ccol + ci * 64 + tx * 4;
            float v[4];
            #pragma unroll
            for (int j = 0; j < 4; j++) v[j] = c[ri * 4 + ii][ci * 4 + j] + bias[n0 + j];
            if (MODE == 0) {
                if (n0 < C_) {
                    #pragma unroll
                    for (int j = 0; j < 4; j++) v[j] = (v[j] + bQ[n0 + j]) * 0.125f; // fold 1/sqrt(64)
                } else if (n0 < 2 * C_) {
                    #pragma unroll
                    for (int j = 0; j < 4; j++) v[j] = v[j] + bK[n0 - C_ + j];
                }
            }
            *(float4*)&Cout[(size_t)r * N + n0] = make_float4(v[0], v[1], v[2], v[3]);
        }
    }
}

// ---------------------------------------------------------------------------
// Flash attention (fp32). One CTA = (b, h, 64-row q tile). Bq=Bk=64, D=64.
// 256 threads as 16(ty: q rows) x 16(tx: k cols / d cols), 4x4 microtiles.
// Smem: Qs natural [i][d]; KP holds K transposed+swizzled [d][j] then is
// reused for P [i][j]; Vs natural [k][d].  3 * 16 KB = 48 KB static.
// ---------------------------------------------------------------------------
__global__ __launch_bounds__(256) void attn_kernel()
{
    __shared__ float Qs[64 * 64];
    __shared__ float KP[64 * 64];
    __shared__ float Vs[64 * 64];

    const int tid = threadIdx.x;
    const int tx = tid & 15, ty = tid >> 4;
    const int qt = blockIdx.x, h = blockIdx.y, b = blockIdx.z;
    const int q0 = qt * 64;
    const size_t rowbase = (size_t)b * T_ * C3_ + (size_t)h * D_;

    // Load Q tile (q already has bQ added and 1/sqrt(D) folded in)
    #pragma unroll
    for (int r = 0; r < 4; r++) {
        int cidx = tid + 256 * r;
        int i = cidx >> 4, f = cidx & 15;
        *(float4*)&Qs[i * 64 + f * 4] =
            *(const float4*)&g_qkv[rowbase + (size_t)(q0 + i) * C3_ + f * 4];
    }

    const float NEG = -1e30f;
    float m[4], l[4], o[4][4];
    #pragma unroll
    for (int ii = 0; ii < 4; ii++) {
        m[ii] = NEG; l[ii] = 0.f;
        #pragma unroll
        for (int j = 0; j < 4; j++) o[ii][j] = 0.f;
    }

    for (int kt = 0; kt <= qt; kt++) {
        const int k0 = kt * 64;
        __syncthreads();  // previous iteration's KP/Vs readers done (also covers Qs store->read)

        // Load K (transposed + XOR swizzle -> conflict-free stores AND reads) and V (natural)
        #pragma unroll
        for (int r = 0; r < 4; r++) {
            int cidx = tid + 256 * r;
            int j = cidx >> 4, f = cidx & 15;       // j = k-row, d = 4f..4f+3
            size_t gro = rowbase + (size_t)(k0 + j) * C3_;
            float4 kv = *(const float4*)&g_qkv[gro + C_ + f * 4];
            int pcol = (((j >> 2) ^ f) << 2) + (j & 3);   // swizzle group by (d>>2)=f
            KP[(4 * f + 0) * 64 + pcol] = kv.x;
            KP[(4 * f + 1) * 64 + pcol] = kv.y;
            KP[(4 * f + 2) * 64 + pcol] = kv.z;
            KP[(4 * f + 3) * 64 + pcol] = kv.w;
            *(float4*)&Vs[j * 64 + f * 4] =
                *(const float4*)&g_qkv[gro + 2 * C_ + f * 4];
        }
        __syncthreads();

        // S = Q K^T  (scale already folded into Q)
        float s[4][4];
        #pragma unroll
        for (int ii = 0; ii < 4; ii++)
            #pragma unroll
            for (int j = 0; j < 4; j++) s[ii][j] = 0.f;

        #pragma unroll 8
        for (int d = 0; d < 64; d++) {
            float a0 = Qs[(ty * 4 + 0) * 64 + d];
            float a1 = Qs[(ty * 4 + 1) * 64 + d];
            float a2 = Qs[(ty * 4 + 2) * 64 + d];
            float a3 = Qs[(ty * 4 + 3) * 64 + d];
            float4 bb = *(const float4*)&KP[d * 64 + ((tx ^ (d >> 2)) << 2)];
            s[0][0] = fmaf(a0, bb.x, s[0][0]); s[0][1] = fmaf(a0, bb.y, s[0][1]);
            s[0][2] = fmaf(a0, bb.z, s[0][2]); s[0][3] = fmaf(a0, bb.w, s[0][3]);
            s[1][0] = fmaf(a1, bb.x, s[1][0]); s[1][1] = fmaf(a1, bb.y, s[1][1]);
            s[1][2] = fmaf(a1, bb.z, s[1][2]); s[1][3] = fmaf(a1, bb.w, s[1][3]);
            s[2][0] = fmaf(a2, bb.x, s[2][0]); s[2][1] = fmaf(a2, bb.y, s[2][1]);
            s[2][2] = fmaf(a2, bb.z, s[2][2]); s[2][3] = fmaf(a2, bb.w, s[2][3]);
            s[3][0] = fmaf(a3, bb.x, s[3][0]); s[3][1] = fmaf(a3, bb.y, s[3][1]);
            s[3][2] = fmaf(a3, bb.z, s[3][2]); s[3][3] = fmaf(a3, bb.w, s[3][3]);
        }

        if (kt == qt) {  // diagonal tile: causal mask (k0 == q0)
            #pragma unroll
            for (int ii = 0; ii < 4; ii++)
                #pragma unroll
                for (int j = 0; j < 4; j++)
                    if (tx * 4 + j > ty * 4 + ii) s[ii][j] = NEG;
        }

        // online softmax (row reductions across 16 tx lanes = half-warp shfl)
        #pragma unroll
        for (int ii = 0; ii < 4; ii++) {
            float mt = fmaxf(fmaxf(s[ii][0], s[ii][1]), fmaxf(s[ii][2], s[ii][3]));
            mt = fmaxf(mt, __shfl_xor_sync(0xffffffffu, mt, 1));
            mt = fmaxf(mt, __shfl_xor_sync(0xffffffffu, mt, 2));
            mt = fmaxf(mt, __shfl_xor_sync(0xffffffffu, mt, 4));
            mt = fmaxf(mt, __shfl_xor_sync(0xffffffffu, mt, 8));
            float mnew = fmaxf(m[ii], mt);
            float alpha = __expf(m[ii] - mnew);
            float sum = 0.f;
            #pragma unroll
            for (int j = 0; j < 4; j++) {
                s[ii][j] = __expf(s[ii][j] - mnew);
                sum += s[ii][j];
            }
            sum += __shfl_xor_sync(0xffffffffu, sum, 1);
            sum += __shfl_xor_sync(0xffffffffu, sum, 2);
            sum += __shfl_xor_sync(0xffffffffu, sum, 4);
            sum += __shfl_xor_sync(0xffffffffu, sum, 8);
            l[ii] = l[ii] * alpha + sum;
            m[ii] = mnew;
            #pragma unroll
            for (int j = 0; j < 4; j++) o[ii][j] *= alpha;
        }

        __syncthreads();   // all K reads of KP done -> safe to overwrite with P
        #pragma unroll
        for (int ii = 0; ii < 4; ii++)
            *(float4*)&KP[(ty * 4 + ii) * 64 + tx * 4] =
                make_float4(s[ii][0], s[ii][1], s[ii][2], s[ii][3]);
        __syncthreads();

        // O += P @ V
        #pragma unroll 8
        for (int k = 0; k < 64; k++) {
            float a0 = KP[(ty * 4 + 0) * 64 + k];
            float a1 = KP[(ty * 4 + 1) * 64 + k];
            float a2 = KP[(ty * 4 + 2) * 64 + k];
            float a3 = KP[(ty * 4 + 3) * 64 + k];
            float4 bv = *(const float4*)&Vs[k * 64 + tx * 4];
            o[0][0] = fmaf(a0, bv.x, o[0][0]); o[0][1] = fmaf(a0, bv.y, o[0][1]);
            o[0][2] = fmaf(a0, bv.z, o[0][2]); o[0][3] = fmaf(a0, bv.w, o[0][3]);
            o[1][0] = fmaf(a1, bv.x, o[1][0]); o[1][1] = fmaf(a1, bv.y, o[1][1]);
            o[1][2] = fmaf(a1, bv.z, o[1][2]); o[1][3] = fmaf(a1, bv.w, o[1][3]);
            o[2][0] = fmaf(a2, bv.x, o[2][0]); o[2][1] = fmaf(a2, bv.y, o[2][1]);
            o[2][2] = fmaf(a2, bv.z, o[2][2]); o[2][3] = fmaf(a2, bv.w, o[2][3]);
            o[3][0] = fmaf(a3, bv.x, o[3][0]); o[3][1] = fmaf(a3, bv.y, o[3][1]);
            o[3][2] = fmaf(a3, bv.z, o[3][2]); o[3][3] = fmaf(a3, bv.w, o[3][3]);
        }
    }

    // normalize and write y in [b, t, h, d] layout (columns h*D + d)
    #pragma unroll
    for (int ii = 0; ii < 4; ii++) {
        float inv = 1.f / l[ii];
        *(float4*)&g_y[(size_t)(b * T_ + q0 + ty * 4 + ii) * C_ + h * D_ + tx * 4] =
            make_float4(o[ii][0] * inv, o[ii][1] * inv, o[ii][2] * inv, o[ii][3] * inv);
    }
}

// ---------------------------------------------------------------------------
extern "C" void kernel_launch(void* const* d_in, const int* in_sizes, int n_in,
                              void* d_out, int out_size)
{
    const float* x      = (const float*)d_in[0];
    const float* W_attn = (const float*)d_in[1];
    const float* b_attn = (const float*)d_in[2];
    const float* bQ     = (const float*)d_in[3];  // [NH, D] flat == C floats
    const float* bK     = (const float*)d_in[4];
    const float* W_proj = (const float*)d_in[5];
    const float* b_proj = (const float*)d_in[6];
    float* out = (float*)d_out;

    float *qkv_p = nullptr, *y_p = nullptr;
    cudaGetSymbolAddress((void**)&qkv_p, g_qkv);  // host-side query, capture-safe
    cudaGetSymbolAddress((void**)&y_p, g_y);

    // 1) qkv = x @ W_attn + b_attn (+bQ,*0.125 | +bK)        [8192, 3072]
    sgemm_kernel<0><<<dim3(C3_ / 128, BT_ / 128), 256>>>(
        x, W_attn, b_attn, bQ, bK, qkv_p, BT_, C3_, C_);

    // 2) flash attention -> g_y                              [8192, 1024]
    attn_kernel<<<dim3(T_ / 64, NH_, B_), 256>>>();

    // 3) out = y @ W_proj + b_proj                           [8192, 1024]
    sgemm_kernel<1><<<dim3(C_ / 128, BT_ / 128), 256>>>(
        y_p, W_proj, b_proj, nullptr, nullptr, out, BT_, C_, C_);
}